// round 3
// baseline (speedup 1.0000x reference)
#include <cuda_runtime.h>
#include <math.h>

#define Bb 4
#define Nn 128
#define Pp 512
#define Hh 64
#define Ee 32
#define Ff 169          // 2*64 + 32 + 3 + 4 + 1 + 1
#define TJ 64           // j-tile
#define NJ (Nn + Pp)    // 640
#define NTILE (NJ / TJ) // 10

struct __align__(16) Smem {
    float Wm1[Ff * 64];     // 169x64
    float Wm2[64 * 64];
    float Wx1[64 * 64];
    float Wx2[64 * 3];
    float bm1[64];
    float bm2[64];
    float bx1[64];
    float bx2[4];
    float feat[TJ * Ff];    // 64 x 169
    float hid[TJ * 65];     // padded stride 65
    float m[TJ * 65];
    float hi[64];
    float msum_part[256];   // 4 groups x 64
    float maskj[TJ];
    float rotq[TJ * 4];
    float xred[TJ * 3];
    float msum[64];
    float hidf[64];
    float hidt[64];
    float hidq[64];
    float traw[16];
    float dqraw[4];
    float xacc[4];
    float qi[4];
    float xi[4];
    float nn;
};

__global__ void __launch_bounds__(256, 1)
egnn_kernel(const float* __restrict__ q, const float* __restrict__ x,
            const float* __restrict__ h, const float* __restrict__ e,
            const int* __restrict__ node_mask,
            const float* __restrict__ pq, const float* __restrict__ px,
            const float* __restrict__ pe, const float* __restrict__ ph,
            const int* __restrict__ pmask,
            const float* __restrict__ Wm1, const float* __restrict__ bm1,
            const float* __restrict__ Wm2, const float* __restrict__ bm2,
            const float* __restrict__ Wf1, const float* __restrict__ bf1,
            const float* __restrict__ Wf2, const float* __restrict__ bf2,
            const float* __restrict__ Wx1, const float* __restrict__ bx1,
            const float* __restrict__ Wx2, const float* __restrict__ bx2,
            const float* __restrict__ Wq1, const float* __restrict__ bq1,
            const float* __restrict__ Wq2, const float* __restrict__ bq2,
            const float* __restrict__ Wt1, const float* __restrict__ bt1,
            const float* __restrict__ Wt2, const float* __restrict__ bt2,
            float* __restrict__ out)
{
    extern __shared__ float smem_raw[];
    Smem* s = (Smem*)smem_raw;
    const int i = blockIdx.x;
    const int b = blockIdx.y;
    const int tid = threadIdx.x;

    // ---- stage weights & node-i data ----
    for (int idx = tid; idx < Ff * 64; idx += 256) s->Wm1[idx] = Wm1[idx];
    for (int idx = tid; idx < 64 * 64; idx += 256) s->Wm2[idx] = Wm2[idx];
    for (int idx = tid; idx < 64 * 64; idx += 256) s->Wx1[idx] = Wx1[idx];
    for (int idx = tid; idx < 64 * 3; idx += 256) s->Wx2[idx] = Wx2[idx];
    if (tid < 64) {
        s->bm1[tid] = bm1[tid];
        s->bm2[tid] = bm2[tid];
        s->bx1[tid] = bx1[tid];
        s->hi[tid] = h[(b * Nn + i) * Hh + tid];
    }
    if (tid < 3) s->bx2[tid] = bx2[tid];
    if (tid < 4) s->qi[tid] = q[(b * Nn + i) * 4 + tid];
    if (tid < 3) s->xi[tid] = x[(b * Nn + i) * 3 + tid];
    s->msum_part[tid] = 0.0f;
    if (tid == 0) s->nn = -1.0f;  // n_neigh has a -1 term
    __syncthreads();

    // n_neigh = sum(node_mask[b]) + sum(pocket_mask[b]) - 1
    {
        float cnt = 0.0f;
        for (int jj = tid; jj < Nn; jj += 256) cnt += node_mask[b * Nn + jj] ? 1.0f : 0.0f;
        for (int jj = tid; jj < Pp; jj += 256) cnt += pmask[b * Pp + jj] ? 1.0f : 0.0f;
        #pragma unroll
        for (int off = 16; off; off >>= 1) cnt += __shfl_down_sync(0xffffffff, cnt, off);
        if ((tid & 31) == 0) atomicAdd(&s->nn, cnt);
    }

    const float qiw = s->qi[0], qix = s->qi[1], qiy = s->qi[2], qiz = s->qi[3];
    const float xi0 = s->xi[0], xi1 = s->xi[1], xi2 = s->xi[2];
    const int mi = node_mask[b * Nn + i];

    float xacc0 = 0.0f, xacc1 = 0.0f, xacc2 = 0.0f;  // only used by tid<64

    const int jb = tid >> 4;      // 0..15 -> j block of 4
    const int cb = tid & 15;      // 0..15 -> t block of 4

    for (int tile = 0; tile < NTILE; tile++) {
        const int j0 = tile * TJ;

        // ---------- Phase A: build feature tile ----------
        for (int idx = tid; idx < TJ * 64; idx += 256) {
            int jl = idx >> 6, t = idx & 63;
            s->feat[jl * Ff + t] = s->hi[t];
        }
        for (int idx = tid; idx < TJ * 64; idx += 256) {
            int jl = idx >> 6, t = idx & 63;
            int j = j0 + jl;
            const float* hrow = (j < Nn) ? &h[(b * Nn + j) * Hh]
                                         : &ph[(b * Pp + (j - Nn)) * Hh];
            s->feat[jl * Ff + 64 + t] = hrow[t];
        }
        for (int idx = tid; idx < TJ * 32; idx += 256) {
            int jl = idx >> 5, c = idx & 31;
            int j = j0 + jl;
            const float* erow = (j < Nn) ? &e[((size_t)(b * Nn + i) * Nn + j) * Ee]
                                         : &pe[((size_t)(b * Nn + i) * Pp + (j - Nn)) * Ee];
            s->feat[jl * Ff + 128 + c] = erow[c];
        }
        if (tid < TJ) {
            int j = j0 + tid;
            float qjw, qjx, qjy, qjz, xj0, xj1, xj2;
            int mj;
            if (j < Nn) {
                const float* qp = &q[(b * Nn + j) * 4];
                qjw = qp[0]; qjx = qp[1]; qjy = qp[2]; qjz = qp[3];
                const float* xp = &x[(b * Nn + j) * 3];
                xj0 = xp[0]; xj1 = xp[1]; xj2 = xp[2];
                mj = (node_mask[b * Nn + j] && (j != i)) ? 1 : 0;
            } else {
                int jp = j - Nn;
                const float* qp = &pq[(b * Pp + jp) * 4];
                qjw = qp[0]; qjx = qp[1]; qjy = qp[2]; qjz = qp[3];
                const float* xp = &px[(b * Pp + jp) * 3];
                xj0 = xp[0]; xj1 = xp[1]; xj2 = xp[2];
                mj = pmask[b * Pp + jp] ? 1 : 0;
            }
            s->maskj[tid] = (mi && mj) ? 1.0f : 0.0f;

            float d0 = xi0 - xj0, d1 = xi1 - xj1, dz = xi2 - xj2;
            float dd = d0 * d0 + d1 * d1 + dz * dz;
            float qd = fabsf(qiw * qjw + qix * qjx + qiy * qjy + qiz * qjz);
            // conj_j vector part
            float vx = -qjx, vy = -qjy, vz = -qjz;
            // local_x = rotate(conj_j, diff)
            float tx = 2.0f * (vy * dz - vz * d1);
            float ty = 2.0f * (vz * d0 - vx * dz);
            float tz = 2.0f * (vx * d1 - vy * d0);
            float lx0 = d0 + qjw * tx + (vy * tz - vz * ty);
            float lx1 = d1 + qjw * ty + (vz * tx - vx * tz);
            float lx2 = dz + qjw * tz + (vx * ty - vy * tx);
            // local_q = quat_mul(conj_j, q_i)
            float lq0 = qjw * qiw - vx * qix - vy * qiy - vz * qiz;
            float lq1 = qjw * qix + vx * qiw + vy * qiz - vz * qiy;
            float lq2 = qjw * qiy - vx * qiz + vy * qiw + vz * qix;
            float lq3 = qjw * qiz + vx * qiy - vy * qix + vz * qiw;
            float* fr = &s->feat[tid * Ff + 160];
            fr[0] = lx0; fr[1] = lx1; fr[2] = lx2;
            fr[3] = lq0; fr[4] = lq1; fr[5] = lq2; fr[6] = lq3;
            fr[7] = dd; fr[8] = qd;
            // rot_j = normalize(q_j)
            float qn = fmaxf(sqrtf(qjw * qjw + qjx * qjx + qjy * qjy + qjz * qjz), 1e-12f);
            float inv = 1.0f / qn;
            s->rotq[tid * 4 + 0] = qjw * inv;
            s->rotq[tid * 4 + 1] = qjx * inv;
            s->rotq[tid * 4 + 2] = qjy * inv;
            s->rotq[tid * 4 + 3] = qjz * inv;
        }
        __syncthreads();

        // ---------- Phase B: hid = relu(feat @ Wm1 + bm1) ----------
        {
            const float* f0 = &s->feat[(jb * 4 + 0) * Ff];
            const float* f1 = f0 + Ff;
            const float* f2 = f1 + Ff;
            const float* f3 = f2 + Ff;
            const float* wp = &s->Wm1[cb * 4];
            float acc[4][4];
            #pragma unroll
            for (int r = 0; r < 4; r++)
                #pragma unroll
                for (int c = 0; c < 4; c++) acc[r][c] = 0.0f;
            #pragma unroll 2
            for (int k = 0; k < Ff; k++) {
                float4 wv = *(const float4*)(wp + (size_t)k * 64);
                float v0 = f0[k], v1 = f1[k], v2 = f2[k], v3 = f3[k];
                acc[0][0] += v0 * wv.x; acc[0][1] += v0 * wv.y; acc[0][2] += v0 * wv.z; acc[0][3] += v0 * wv.w;
                acc[1][0] += v1 * wv.x; acc[1][1] += v1 * wv.y; acc[1][2] += v1 * wv.z; acc[1][3] += v1 * wv.w;
                acc[2][0] += v2 * wv.x; acc[2][1] += v2 * wv.y; acc[2][2] += v2 * wv.z; acc[2][3] += v2 * wv.w;
                acc[3][0] += v3 * wv.x; acc[3][1] += v3 * wv.y; acc[3][2] += v3 * wv.z; acc[3][3] += v3 * wv.w;
            }
            #pragma unroll
            for (int r = 0; r < 4; r++)
                #pragma unroll
                for (int c = 0; c < 4; c++)
                    s->hid[(jb * 4 + r) * 65 + cb * 4 + c] =
                        fmaxf(acc[r][c] + s->bm1[cb * 4 + c], 0.0f);
        }
        __syncthreads();

        // ---------- Phase C: m = (hid @ Wm2 + bm2) * mask ----------
        {
            const float* wp = &s->Wm2[cb * 4];
            float acc[4][4];
            #pragma unroll
            for (int r = 0; r < 4; r++)
                #pragma unroll
                for (int c = 0; c < 4; c++) acc[r][c] = 0.0f;
            #pragma unroll 2
            for (int k = 0; k < 64; k++) {
                float4 wv = *(const float4*)(wp + (size_t)k * 64);
                float v0 = s->hid[(jb * 4 + 0) * 65 + k];
                float v1 = s->hid[(jb * 4 + 1) * 65 + k];
                float v2 = s->hid[(jb * 4 + 2) * 65 + k];
                float v3 = s->hid[(jb * 4 + 3) * 65 + k];
                acc[0][0] += v0 * wv.x; acc[0][1] += v0 * wv.y; acc[0][2] += v0 * wv.z; acc[0][3] += v0 * wv.w;
                acc[1][0] += v1 * wv.x; acc[1][1] += v1 * wv.y; acc[1][2] += v1 * wv.z; acc[1][3] += v1 * wv.w;
                acc[2][0] += v2 * wv.x; acc[2][1] += v2 * wv.y; acc[2][2] += v2 * wv.z; acc[2][3] += v2 * wv.w;
                acc[3][0] += v3 * wv.x; acc[3][1] += v3 * wv.y; acc[3][2] += v3 * wv.z; acc[3][3] += v3 * wv.w;
            }
            #pragma unroll
            for (int r = 0; r < 4; r++) {
                float mk = s->maskj[jb * 4 + r];
                #pragma unroll
                for (int c = 0; c < 4; c++)
                    s->m[(jb * 4 + r) * 65 + cb * 4 + c] =
                        (acc[r][c] + s->bm2[cb * 4 + c]) * mk;
            }
        }
        __syncthreads();

        // ---------- Phase M: msum partial ----------
        {
            int t = tid & 63, g = tid >> 6;
            float ps = 0.0f;
            #pragma unroll
            for (int jl = 0; jl < 16; jl++) ps += s->m[(g * 16 + jl) * 65 + t];
            s->msum_part[g * 64 + t] += ps;
        }
        __syncthreads();

        // ---------- Phase D: hid2 = relu(m @ Wx1 + bx1) (into hid) ----------
        {
            const float* wp = &s->Wx1[cb * 4];
            float acc[4][4];
            #pragma unroll
            for (int r = 0; r < 4; r++)
                #pragma unroll
                for (int c = 0; c < 4; c++) acc[r][c] = 0.0f;
            #pragma unroll 2
            for (int k = 0; k < 64; k++) {
                float4 wv = *(const float4*)(wp + (size_t)k * 64);
                float v0 = s->m[(jb * 4 + 0) * 65 + k];
                float v1 = s->m[(jb * 4 + 1) * 65 + k];
                float v2 = s->m[(jb * 4 + 2) * 65 + k];
                float v3 = s->m[(jb * 4 + 3) * 65 + k];
                acc[0][0] += v0 * wv.x; acc[0][1] += v0 * wv.y; acc[0][2] += v0 * wv.z; acc[0][3] += v0 * wv.w;
                acc[1][0] += v1 * wv.x; acc[1][1] += v1 * wv.y; acc[1][2] += v1 * wv.z; acc[1][3] += v1 * wv.w;
                acc[2][0] += v2 * wv.x; acc[2][1] += v2 * wv.y; acc[2][2] += v2 * wv.z; acc[2][3] += v2 * wv.w;
                acc[3][0] += v3 * wv.x; acc[3][1] += v3 * wv.y; acc[3][2] += v3 * wv.z; acc[3][3] += v3 * wv.w;
            }
            #pragma unroll
            for (int r = 0; r < 4; r++)
                #pragma unroll
                for (int c = 0; c < 4; c++)
                    s->hid[(jb * 4 + r) * 65 + cb * 4 + c] =
                        fmaxf(acc[r][c] + s->bx1[cb * 4 + c], 0.0f);
        }
        __syncthreads();

        // ---------- Phase E: dx -> rotate -> accumulate ----------
        if (tid < TJ) {
            float a0 = s->bx2[0], a1 = s->bx2[1], a2 = s->bx2[2];
            #pragma unroll 4
            for (int u = 0; u < 64; u++) {
                float hv = s->hid[tid * 65 + u];
                a0 += hv * s->Wx2[u * 3 + 0];
                a1 += hv * s->Wx2[u * 3 + 1];
                a2 += hv * s->Wx2[u * 3 + 2];
            }
            float mk = s->maskj[tid];
            a0 *= mk; a1 *= mk; a2 *= mk;
            float w  = s->rotq[tid * 4 + 0];
            float vx = s->rotq[tid * 4 + 1];
            float vy = s->rotq[tid * 4 + 2];
            float vz = s->rotq[tid * 4 + 3];
            float tx = 2.0f * (vy * a2 - vz * a1);
            float ty = 2.0f * (vz * a0 - vx * a2);
            float tz = 2.0f * (vx * a1 - vy * a0);
            xacc0 += a0 + w * tx + (vy * tz - vz * ty);
            xacc1 += a1 + w * ty + (vz * tx - vx * tz);
            xacc2 += a2 + w * tz + (vx * ty - vy * tx);
        }
        __syncthreads();
    }

    // ---- final msum & xacc staging ----
    if (tid < 64) {
        s->msum[tid] = s->msum_part[tid] + s->msum_part[64 + tid] +
                       s->msum_part[128 + tid] + s->msum_part[192 + tid];
    }
    if (tid < TJ) {
        s->xred[tid * 3 + 0] = xacc0;
        s->xred[tid * 3 + 1] = xacc1;
        s->xred[tid * 3 + 2] = xacc2;
    }
    __syncthreads();

    const int grp = tid >> 6, lt = tid & 63;
    // ---- epilogue hidden layers (3 groups of 64) + xacc reduce ----
    if (grp == 0) {
        float acc = bf1[lt];
        #pragma unroll 4
        for (int k = 0; k < 64; k++) acc += s->hi[k] * Wf1[k * 64 + lt];
        #pragma unroll 4
        for (int k = 0; k < 64; k++) acc += s->msum[k] * Wf1[(64 + k) * 64 + lt];
        s->hidf[lt] = fmaxf(acc, 0.0f);
    } else if (grp == 1) {
        float acc = bt1[lt];
        #pragma unroll 4
        for (int k = 0; k < 64; k++) acc += s->msum[k] * Wt1[k * 64 + lt];
        s->hidt[lt] = fmaxf(acc, 0.0f);
    } else if (grp == 2) {
        float acc = bq1[lt];
        #pragma unroll 4
        for (int k = 0; k < 64; k++) acc += s->msum[k] * Wq1[k * 64 + lt];
        s->hidq[lt] = fmaxf(acc, 0.0f);
    } else if (lt < 3) {
        float sum = 0.0f;
        #pragma unroll 4
        for (int j = 0; j < TJ; j++) sum += s->xred[j * 3 + lt];
        s->xacc[lt] = sum;
    }
    __syncthreads();

    float* out_q = out;
    float* out_x = out + Bb * Nn * 4;
    float* out_t = out + Bb * Nn * 7;
    float* out_o = out + Bb * Nn * 21;
    const int node = b * Nn + i;

    if (grp == 0) {
        float acc = bf2[lt];
        #pragma unroll 4
        for (int u = 0; u < 64; u++) acc += s->hidf[u] * Wf2[u * 64 + lt];
        out_o[node * 64 + lt] = acc;
    } else if (grp == 1 && lt < 14) {
        float acc = bt2[lt];
        #pragma unroll 4
        for (int u = 0; u < 64; u++) acc += s->hidt[u] * Wt2[u * 14 + lt];
        s->traw[lt] = acc;
    } else if (grp == 2 && lt < 4) {
        float acc = bq2[lt];
        #pragma unroll 4
        for (int u = 0; u < 64; u++) acc += s->hidq[u] * Wq2[u * 4 + lt];
        s->dqraw[lt] = acc;
    }
    __syncthreads();

    if (tid == 0) {
        float d0 = s->dqraw[0], d1 = s->dqraw[1], d2 = s->dqraw[2], d3 = s->dqraw[3];
        if (!mi) { d0 = 1.0f; d1 = 0.0f; d2 = 0.0f; d3 = 0.0f; }
        float nrm = fmaxf(sqrtf(d0 * d0 + d1 * d1 + d2 * d2 + d3 * d3), 1e-12f);
        float inv = 1.0f / nrm;
        d0 *= inv; d1 *= inv; d2 *= inv; d3 *= inv;
        float u0 = qiw * d0 - qix * d1 - qiy * d2 - qiz * d3;
        float u1 = qiw * d1 + qix * d0 + qiy * d3 - qiz * d2;
        float u2 = qiw * d2 - qix * d3 + qiy * d0 + qiz * d1;
        float u3 = qiw * d3 + qix * d2 - qiy * d1 + qiz * d0;
        if (!mi) { u0 = 1.0f; u1 = 0.0f; u2 = 0.0f; u3 = 0.0f; }
        nrm = fmaxf(sqrtf(u0 * u0 + u1 * u1 + u2 * u2 + u3 * u3), 1e-12f);
        inv = 1.0f / nrm;
        out_q[node * 4 + 0] = u0 * inv;
        out_q[node * 4 + 1] = u1 * inv;
        out_q[node * 4 + 2] = u2 * inv;
        out_q[node * 4 + 3] = u3 * inv;
    }
    if (tid >= 4 && tid < 7) {
        int c = tid - 4;
        out_x[node * 3 + c] = s->xi[c] + s->xacc[c] / s->nn;
    }
    if (tid >= 32 && tid < 39) {
        int p = tid - 32;
        float a = s->traw[p * 2 + 0];
        float c = s->traw[p * 2 + 1];
        float nrm = fmaxf(sqrtf(a * a + c * c), 1e-12f);
        out_t[node * 14 + p * 2 + 0] = a / nrm;
        out_t[node * 14 + p * 2 + 1] = c / nrm;
    }
}

extern "C" void kernel_launch(void* const* d_in, const int* in_sizes, int n_in,
                              void* d_out, int out_size)
{
    const float* q  = (const float*)d_in[0];
    const float* x  = (const float*)d_in[1];
    // d_in[2] = torsions (only its shape matters; values unused)
    const float* h  = (const float*)d_in[3];
    const float* e  = (const float*)d_in[4];
    const int* node_mask = (const int*)d_in[5];
    const float* pq = (const float*)d_in[6];
    const float* px = (const float*)d_in[7];
    const float* pe = (const float*)d_in[8];
    const float* ph = (const float*)d_in[9];
    const int* pmask = (const int*)d_in[10];
    const float* Wm1 = (const float*)d_in[11];
    const float* bm1 = (const float*)d_in[12];
    const float* Wm2 = (const float*)d_in[13];
    const float* bm2 = (const float*)d_in[14];
    const float* Wf1 = (const float*)d_in[15];
    const float* bf1 = (const float*)d_in[16];
    const float* Wf2 = (const float*)d_in[17];
    const float* bf2 = (const float*)d_in[18];
    const float* Wx1 = (const float*)d_in[19];
    const float* bx1 = (const float*)d_in[20];
    const float* Wx2 = (const float*)d_in[21];
    const float* bx2 = (const float*)d_in[22];
    const float* Wq1 = (const float*)d_in[23];
    const float* bq1 = (const float*)d_in[24];
    const float* Wq2 = (const float*)d_in[25];
    const float* bq2 = (const float*)d_in[26];
    const float* Wt1 = (const float*)d_in[27];
    const float* bt1 = (const float*)d_in[28];
    const float* Wt2 = (const float*)d_in[29];
    const float* bt2 = (const float*)d_in[30];

    const size_t smem = sizeof(Smem);
    cudaFuncSetAttribute(egnn_kernel, cudaFuncAttributeMaxDynamicSharedMemorySize,
                         (int)smem);

    dim3 grid(Nn, Bb);
    egnn_kernel<<<grid, 256, smem>>>(
        q, x, h, e, node_mask, pq, px, pe, ph, pmask,
        Wm1, bm1, Wm2, bm2, Wf1, bf1, Wf2, bf2,
        Wx1, bx1, Wx2, bx2, Wq1, bq1, Wq2, bq2, Wt1, bt1, Wt2, bt2,
        (float*)d_out);
}

// round 5
// speedup vs baseline: 2.2591x; 2.2591x over previous
#include <cuda_runtime.h>
#include <math.h>

#define Bb 4
#define Nn 128
#define Pp 512
#define Ee 32
#define Ff 169          // 2*64 + 32 + 3 + 4 + 1 + 1
#define FfP 172         // padded to multiple of 4 (zero-filled)
#define TJ 128          // j-tile rows
#define NTILE 5         // 640 / 128
#define HS 68           // hid/m row stride (floats, mult of 4)
#define NT 512          // threads per CTA

struct __align__(16) Smem {
    float Wm1[FfP * 64];   // 172x64 (rows 169..171 zeroed)
    float Wm2[64 * 64];
    float Wx1[64 * 64];
    float Wx2[64 * 3];
    float bm1[64];
    float bm2[64];
    float bx1[64];
    float bx2[4];
    float feat[TJ * FfP];  // 128 x 172 ; reused as m (stride HS) after Phase B
    float hid[TJ * HS];    // 128 x 68
    float hi[64];
    float maskj[TJ];
    float rotq[TJ * 4];
    float xred[TJ * 3];
    float msum_part[8 * 64];
    float msum[64];
    float hidf[64];
    float hidt[64];
    float hidq[64];
    float traw[16];
    float dqraw[4];
    float xacc[4];
    float qi[4];
    float xi[4];
    float nn;
};

#define RANK1(CMP_, WV_) \
    acc[0][0] += a0.CMP_ * WV_.x; acc[0][1] += a0.CMP_ * WV_.y; acc[0][2] += a0.CMP_ * WV_.z; acc[0][3] += a0.CMP_ * WV_.w; \
    acc[1][0] += a1.CMP_ * WV_.x; acc[1][1] += a1.CMP_ * WV_.y; acc[1][2] += a1.CMP_ * WV_.z; acc[1][3] += a1.CMP_ * WV_.w; \
    acc[2][0] += a2.CMP_ * WV_.x; acc[2][1] += a2.CMP_ * WV_.y; acc[2][2] += a2.CMP_ * WV_.z; acc[2][3] += a2.CMP_ * WV_.w; \
    acc[3][0] += a3.CMP_ * WV_.x; acc[3][1] += a3.CMP_ * WV_.y; acc[3][2] += a3.CMP_ * WV_.z; acc[3][3] += a3.CMP_ * WV_.w;

// 4x4 output tile, fully vectorized k: src = 4 rows at stride SSTRIDE,
// wcol = weight column block (4 cols), weight row stride 64 floats.
template<int KVCOUNT, int SSTRIDE>
__device__ __forceinline__ void gemm16(const float* __restrict__ src,
                                       const float* __restrict__ wcol,
                                       float acc[4][4])
{
    #pragma unroll 2
    for (int kv = 0; kv < KVCOUNT; kv++) {
        float4 a0 = *(const float4*)(src + 0 * SSTRIDE + kv * 4);
        float4 a1 = *(const float4*)(src + 1 * SSTRIDE + kv * 4);
        float4 a2 = *(const float4*)(src + 2 * SSTRIDE + kv * 4);
        float4 a3 = *(const float4*)(src + 3 * SSTRIDE + kv * 4);
        float4 w0 = *(const float4*)(wcol + (kv * 4 + 0) * 64);
        float4 w1 = *(const float4*)(wcol + (kv * 4 + 1) * 64);
        float4 w2 = *(const float4*)(wcol + (kv * 4 + 2) * 64);
        float4 w3 = *(const float4*)(wcol + (kv * 4 + 3) * 64);
        RANK1(x, w0)
        RANK1(y, w1)
        RANK1(z, w2)
        RANK1(w, w3)
    }
}

__global__ void __launch_bounds__(NT, 1)
egnn_kernel(const float* __restrict__ q, const float* __restrict__ x,
            const float* __restrict__ h, const float* __restrict__ e,
            const int* __restrict__ node_mask,
            const float* __restrict__ pq, const float* __restrict__ px,
            const float* __restrict__ pe, const float* __restrict__ ph,
            const int* __restrict__ pmask,
            const float* __restrict__ Wm1, const float* __restrict__ bm1,
            const float* __restrict__ Wm2, const float* __restrict__ bm2,
            const float* __restrict__ Wf1, const float* __restrict__ bf1,
            const float* __restrict__ Wf2, const float* __restrict__ bf2,
            const float* __restrict__ Wx1, const float* __restrict__ bx1,
            const float* __restrict__ Wx2, const float* __restrict__ bx2,
            const float* __restrict__ Wq1, const float* __restrict__ bq1,
            const float* __restrict__ Wq2, const float* __restrict__ bq2,
            const float* __restrict__ Wt1, const float* __restrict__ bt1,
            const float* __restrict__ Wt2, const float* __restrict__ bt2,
            float* __restrict__ out)
{
    extern __shared__ float smem_raw[];
    Smem* s = (Smem*)smem_raw;
    const int i = blockIdx.x;
    const int b = blockIdx.y;
    const int tid = threadIdx.x;

    // ---- stage weights (vectorized) & node-i data ----
    {
        const float4* g4 = (const float4*)Wm1;
        float4* s4 = (float4*)s->Wm1;
        for (int idx = tid; idx < Ff * 16; idx += NT) s4[idx] = g4[idx];
        for (int idx = tid; idx < 3 * 64; idx += NT) s->Wm1[Ff * 64 + idx] = 0.0f;
        g4 = (const float4*)Wm2; s4 = (float4*)s->Wm2;
        for (int idx = tid; idx < 1024; idx += NT) s4[idx] = g4[idx];
        g4 = (const float4*)Wx1; s4 = (float4*)s->Wx1;
        for (int idx = tid; idx < 1024; idx += NT) s4[idx] = g4[idx];
        g4 = (const float4*)Wx2; s4 = (float4*)s->Wx2;
        for (int idx = tid; idx < 48; idx += NT) s4[idx] = g4[idx];
    }
    if (tid < 64) {
        s->bm1[tid] = bm1[tid];
        s->bm2[tid] = bm2[tid];
        s->bx1[tid] = bx1[tid];
        s->hi[tid] = h[(b * Nn + i) * 64 + tid];
    }
    if (tid < 3) s->bx2[tid] = bx2[tid];
    if (tid < 4) s->qi[tid] = q[(b * Nn + i) * 4 + tid];
    if (tid < 3) s->xi[tid] = x[(b * Nn + i) * 3 + tid];
    if (tid < 8 * 64) s->msum_part[tid] = 0.0f;
    if (tid == 0) s->nn = -1.0f;  // n_neigh has a -1 term
    __syncthreads();

    // n_neigh = sum(node_mask[b]) + sum(pocket_mask[b]) - 1
    {
        float cnt = 0.0f;
        for (int jj = tid; jj < Nn; jj += NT) cnt += node_mask[b * Nn + jj] ? 1.0f : 0.0f;
        for (int jj = tid; jj < Pp; jj += NT) cnt += pmask[b * Pp + jj] ? 1.0f : 0.0f;
        #pragma unroll
        for (int off = 16; off; off >>= 1) cnt += __shfl_down_sync(0xffffffff, cnt, off);
        if ((tid & 31) == 0) atomicAdd(&s->nn, cnt);
    }

    const float qiw = s->qi[0], qix = s->qi[1], qiy = s->qi[2], qiz = s->qi[3];
    const float xi0 = s->xi[0], xi1 = s->xi[1], xi2 = s->xi[2];
    const int mi = node_mask[b * Nn + i];

    float xacc0 = 0.0f, xacc1 = 0.0f, xacc2 = 0.0f;  // live in tid<128 only

    const int jb = tid >> 4;      // 0..31 -> block of 4 j rows
    const int cb = tid & 15;      // 0..15 -> block of 4 output cols
    float* const mb = s->feat;    // m overlay (stride HS)

    for (int tile = 0; tile < NTILE; tile++) {
        const int j0 = tile * TJ;

        // ---------- Phase A: build feature tile ----------
        for (int idx = tid; idx < TJ * 16; idx += NT) {
            int row = idx >> 4, c = idx & 15;
            *(float4*)&s->feat[row * FfP + c * 4] = *(const float4*)&s->hi[c * 4];
        }
        for (int idx = tid; idx < TJ * 16; idx += NT) {
            int row = idx >> 4, c = idx & 15;
            int j = j0 + row;
            const float4* hrow = (j < Nn) ? (const float4*)&h[(b * Nn + j) * 64]
                                          : (const float4*)&ph[(b * Pp + (j - Nn)) * 64];
            *(float4*)&s->feat[row * FfP + 64 + c * 4] = hrow[c];
        }
        for (int idx = tid; idx < TJ * 8; idx += NT) {
            int row = idx >> 3, c = idx & 7;
            int j = j0 + row;
            const float4* erow = (j < Nn)
                ? (const float4*)&e[((size_t)(b * Nn + i) * Nn + j) * Ee]
                : (const float4*)&pe[((size_t)(b * Nn + i) * Pp + (j - Nn)) * Ee];
            *(float4*)&s->feat[row * FfP + 128 + c * 4] = erow[c];
        }
        if (tid < TJ) {
            int j = j0 + tid;
            float qjw, qjx, qjy, qjz, xj0, xj1, xj2;
            int mj;
            if (j < Nn) {
                const float* qp = &q[(b * Nn + j) * 4];
                qjw = qp[0]; qjx = qp[1]; qjy = qp[2]; qjz = qp[3];
                const float* xp = &x[(b * Nn + j) * 3];
                xj0 = xp[0]; xj1 = xp[1]; xj2 = xp[2];
                mj = (node_mask[b * Nn + j] && (j != i)) ? 1 : 0;
            } else {
                int jp = j - Nn;
                const float* qp = &pq[(b * Pp + jp) * 4];
                qjw = qp[0]; qjx = qp[1]; qjy = qp[2]; qjz = qp[3];
                const float* xp = &px[(b * Pp + jp) * 3];
                xj0 = xp[0]; xj1 = xp[1]; xj2 = xp[2];
                mj = pmask[b * Pp + jp] ? 1 : 0;
            }
            s->maskj[tid] = (mi && mj) ? 1.0f : 0.0f;

            float d0 = xi0 - xj0, d1 = xi1 - xj1, dz = xi2 - xj2;
            float dd = d0 * d0 + d1 * d1 + dz * dz;
            float qd = fabsf(qiw * qjw + qix * qjx + qiy * qjy + qiz * qjz);
            float vx = -qjx, vy = -qjy, vz = -qjz;      // conj_j vector part
            float tx = 2.0f * (vy * dz - vz * d1);
            float ty = 2.0f * (vz * d0 - vx * dz);
            float tz = 2.0f * (vx * d1 - vy * d0);
            float lx0 = d0 + qjw * tx + (vy * tz - vz * ty);
            float lx1 = d1 + qjw * ty + (vz * tx - vx * tz);
            float lx2 = dz + qjw * tz + (vx * ty - vy * tx);
            float lq0 = qjw * qiw - vx * qix - vy * qiy - vz * qiz;
            float lq1 = qjw * qix + vx * qiw + vy * qiz - vz * qiy;
            float lq2 = qjw * qiy - vx * qiz + vy * qiw + vz * qix;
            float lq3 = qjw * qiz + vx * qiy - vy * qix + vz * qiw;
            float* fr = &s->feat[tid * FfP + 160];
            fr[0] = lx0; fr[1] = lx1; fr[2] = lx2;
            fr[3] = lq0; fr[4] = lq1; fr[5] = lq2; fr[6] = lq3;
            fr[7] = dd; fr[8] = qd;
            fr[9] = 0.0f; fr[10] = 0.0f; fr[11] = 0.0f;  // zero pad to 172
            float qn = fmaxf(sqrtf(qjw * qjw + qjx * qjx + qjy * qjy + qjz * qjz), 1e-12f);
            float inv = 1.0f / qn;
            s->rotq[tid * 4 + 0] = qjw * inv;
            s->rotq[tid * 4 + 1] = qjx * inv;
            s->rotq[tid * 4 + 2] = qjy * inv;
            s->rotq[tid * 4 + 3] = qjz * inv;
        }
        __syncthreads();

        // ---------- Phase B: hid = relu(feat @ Wm1 + bm1) ----------
        {
            float acc[4][4] = {};
            gemm16<FfP / 4, FfP>(&s->feat[(jb * 4) * FfP], &s->Wm1[cb * 4], acc);
            float4 bb = *(const float4*)&s->bm1[cb * 4];
            float* hr = &s->hid[(jb * 4) * HS + cb * 4];
            #pragma unroll
            for (int r = 0; r < 4; r++) {
                float4 o;
                o.x = fmaxf(acc[r][0] + bb.x, 0.0f);
                o.y = fmaxf(acc[r][1] + bb.y, 0.0f);
                o.z = fmaxf(acc[r][2] + bb.z, 0.0f);
                o.w = fmaxf(acc[r][3] + bb.w, 0.0f);
                *(float4*)(hr + r * HS) = o;
            }
        }
        __syncthreads();

        // ---------- Phase C: m = (hid @ Wm2 + bm2) * mask  (into feat buffer) ----------
        {
            float acc[4][4] = {};
            gemm16<16, HS>(&s->hid[(jb * 4) * HS], &s->Wm2[cb * 4], acc);
            float4 bb = *(const float4*)&s->bm2[cb * 4];
            float* mr = &mb[(jb * 4) * HS + cb * 4];
            #pragma unroll
            for (int r = 0; r < 4; r++) {
                float mk = s->maskj[jb * 4 + r];
                float4 o;
                o.x = (acc[r][0] + bb.x) * mk;
                o.y = (acc[r][1] + bb.y) * mk;
                o.z = (acc[r][2] + bb.z) * mk;
                o.w = (acc[r][3] + bb.w) * mk;
                *(float4*)(mr + r * HS) = o;
            }
        }
        __syncthreads();

        // ---------- Phase M: msum partial (reads m) ----------
        {
            int t = tid & 63, g = tid >> 6;
            float ps = 0.0f;
            #pragma unroll
            for (int r = 0; r < 16; r++) ps += mb[(g * 16 + r) * HS + t];
            s->msum_part[g * 64 + t] += ps;
        }

        // ---------- Phase D: hid = relu(m @ Wx1 + bx1) ----------
        {
            float acc[4][4] = {};
            gemm16<16, HS>(&mb[(jb * 4) * HS], &s->Wx1[cb * 4], acc);
            float4 bb = *(const float4*)&s->bx1[cb * 4];
            float* hr = &s->hid[(jb * 4) * HS + cb * 4];
            #pragma unroll
            for (int r = 0; r < 4; r++) {
                float4 o;
                o.x = fmaxf(acc[r][0] + bb.x, 0.0f);
                o.y = fmaxf(acc[r][1] + bb.y, 0.0f);
                o.z = fmaxf(acc[r][2] + bb.z, 0.0f);
                o.w = fmaxf(acc[r][3] + bb.w, 0.0f);
                *(float4*)(hr + r * HS) = o;
            }
        }
        __syncthreads();

        // ---------- Phase E: dx -> rotate -> accumulate ----------
        if (tid < TJ) {
            float a0 = s->bx2[0], a1 = s->bx2[1], a2 = s->bx2[2];
            const float* hr = &s->hid[tid * HS];
            #pragma unroll 4
            for (int u = 0; u < 64; u++) {
                float hv = hr[u];
                a0 += hv * s->Wx2[u * 3 + 0];
                a1 += hv * s->Wx2[u * 3 + 1];
                a2 += hv * s->Wx2[u * 3 + 2];
            }
            float mk = s->maskj[tid];
            a0 *= mk; a1 *= mk; a2 *= mk;
            float w  = s->rotq[tid * 4 + 0];
            float vx = s->rotq[tid * 4 + 1];
            float vy = s->rotq[tid * 4 + 2];
            float vz = s->rotq[tid * 4 + 3];
            float tx = 2.0f * (vy * a2 - vz * a1);
            float ty = 2.0f * (vz * a0 - vx * a2);
            float tz = 2.0f * (vx * a1 - vy * a0);
            xacc0 += a0 + w * tx + (vy * tz - vz * ty);
            xacc1 += a1 + w * ty + (vz * tx - vx * tz);
            xacc2 += a2 + w * tz + (vx * ty - vy * tx);
        }
        __syncthreads();
    }

    // ---- final msum & xacc staging ----
    if (tid < 64) {
        float acc = 0.0f;
        #pragma unroll
        for (int g = 0; g < 8; g++) acc += s->msum_part[g * 64 + tid];
        s->msum[tid] = acc;
    }
    if (tid < TJ) {
        s->xred[tid * 3 + 0] = xacc0;
        s->xred[tid * 3 + 1] = xacc1;
        s->xred[tid * 3 + 2] = xacc2;
    }
    __syncthreads();

    const int grp = tid >> 6, lt = tid & 63;
    // ---- epilogue hidden layers + xacc reduce ----
    if (grp == 0) {
        float acc = bf1[lt];
        #pragma unroll 4
        for (int k = 0; k < 64; k++) acc += s->hi[k] * Wf1[k * 64 + lt];
        #pragma unroll 4
        for (int k = 0; k < 64; k++) acc += s->msum[k] * Wf1[(64 + k) * 64 + lt];
        s->hidf[lt] = fmaxf(acc, 0.0f);
    } else if (grp == 1) {
        float acc = bt1[lt];
        #pragma unroll 4
        for (int k = 0; k < 64; k++) acc += s->msum[k] * Wt1[k * 64 + lt];
        s->hidt[lt] = fmaxf(acc, 0.0f);
    } else if (grp == 2) {
        float acc = bq1[lt];
        #pragma unroll 4
        for (int k = 0; k < 64; k++) acc += s->msum[k] * Wq1[k * 64 + lt];
        s->hidq[lt] = fmaxf(acc, 0.0f);
    } else if (grp == 3 && lt < 3) {
        float sum = 0.0f;
        #pragma unroll 4
        for (int j = 0; j < TJ; j++) sum += s->xred[j * 3 + lt];
        s->xacc[lt] = sum;
    }
    __syncthreads();

    float* out_q = out;
    float* out_x = out + Bb * Nn * 4;
    float* out_t = out + Bb * Nn * 7;
    float* out_o = out + Bb * Nn * 21;
    const int node = b * Nn + i;

    if (grp == 0) {
        float acc = bf2[lt];
        #pragma unroll 4
        for (int u = 0; u < 64; u++) acc += s->hidf[u] * Wf2[u * 64 + lt];
        out_o[node * 64 + lt] = acc;
    } else if (grp == 1 && lt < 14) {
        float acc = bt2[lt];
        #pragma unroll 4
        for (int u = 0; u < 64; u++) acc += s->hidt[u] * Wt2[u * 14 + lt];
        s->traw[lt] = acc;
    } else if (grp == 2 && lt < 4) {
        float acc = bq2[lt];
        #pragma unroll 4
        for (int u = 0; u < 64; u++) acc += s->hidq[u] * Wq2[u * 4 + lt];
        s->dqraw[lt] = acc;
    }
    __syncthreads();

    if (tid == 0) {
        float d0 = s->dqraw[0], d1 = s->dqraw[1], d2 = s->dqraw[2], d3 = s->dqraw[3];
        if (!mi) { d0 = 1.0f; d1 = 0.0f; d2 = 0.0f; d3 = 0.0f; }
        float nrm = fmaxf(sqrtf(d0 * d0 + d1 * d1 + d2 * d2 + d3 * d3), 1e-12f);
        float inv = 1.0f / nrm;
        d0 *= inv; d1 *= inv; d2 *= inv; d3 *= inv;
        float u0 = qiw * d0 - qix * d1 - qiy * d2 - qiz * d3;
        float u1 = qiw * d1 + qix * d0 + qiy * d3 - qiz * d2;
        float u2 = qiw * d2 - qix * d3 + qiy * d0 + qiz * d1;
        float u3 = qiw * d3 + qix * d2 - qiy * d1 + qiz * d0;
        if (!mi) { u0 = 1.0f; u1 = 0.0f; u2 = 0.0f; u3 = 0.0f; }
        nrm = fmaxf(sqrtf(u0 * u0 + u1 * u1 + u2 * u2 + u3 * u3), 1e-12f);
        inv = 1.0f / nrm;
        out_q[node * 4 + 0] = u0 * inv;
        out_q[node * 4 + 1] = u1 * inv;
        out_q[node * 4 + 2] = u2 * inv;
        out_q[node * 4 + 3] = u3 * inv;
    }
    if (tid >= 4 && tid < 7) {
        int c = tid - 4;
        out_x[node * 3 + c] = s->xi[c] + s->xacc[c] / s->nn;
    }
    if (tid >= 32 && tid < 39) {
        int p = tid - 32;
        float a = s->traw[p * 2 + 0];
        float c = s->traw[p * 2 + 1];
        float nrm = fmaxf(sqrtf(a * a + c * c), 1e-12f);
        out_t[node * 14 + p * 2 + 0] = a / nrm;
        out_t[node * 14 + p * 2 + 1] = c / nrm;
    }
}

extern "C" void kernel_launch(void* const* d_in, const int* in_sizes, int n_in,
                              void* d_out, int out_size)
{
    const float* q  = (const float*)d_in[0];
    const float* x  = (const float*)d_in[1];
    // d_in[2] = torsions (values unused)
    const float* h  = (const float*)d_in[3];
    const float* e  = (const float*)d_in[4];
    const int* node_mask = (const int*)d_in[5];
    const float* pq = (const float*)d_in[6];
    const float* px = (const float*)d_in[7];
    const float* pe = (const float*)d_in[8];
    const float* ph = (const float*)d_in[9];
    const int* pmask = (const int*)d_in[10];
    const float* Wm1 = (const float*)d_in[11];
    const float* bm1 = (const float*)d_in[12];
    const float* Wm2 = (const float*)d_in[13];
    const float* bm2 = (const float*)d_in[14];
    const float* Wf1 = (const float*)d_in[15];
    const float* bf1 = (const float*)d_in[16];
    const float* Wf2 = (const float*)d_in[17];
    const float* bf2 = (const float*)d_in[18];
    const float* Wx1 = (const float*)d_in[19];
    const float* bx1 = (const float*)d_in[20];
    const float* Wx2 = (const float*)d_in[21];
    const float* bx2 = (const float*)d_in[22];
    const float* Wq1 = (const float*)d_in[23];
    const float* bq1 = (const float*)d_in[24];
    const float* Wq2 = (const float*)d_in[25];
    const float* bq2 = (const float*)d_in[26];
    const float* Wt1 = (const float*)d_in[27];
    const float* bt1 = (const float*)d_in[28];
    const float* Wt2 = (const float*)d_in[29];
    const float* bt2 = (const float*)d_in[30];

    const size_t smem = sizeof(Smem);
    cudaFuncSetAttribute(egnn_kernel, cudaFuncAttributeMaxDynamicSharedMemorySize,
                         (int)smem);

    dim3 grid(Nn, Bb);
    egnn_kernel<<<grid, NT, smem>>>(
        q, x, h, e, node_mask, pq, px, pe, ph, pmask,
        Wm1, bm1, Wm2, bm2, Wf1, bf1, Wf2, bf2,
        Wx1, bx1, Wx2, bx2, Wq1, bq1, Wq2, bq2, Wt1, bt1, Wt2, bt2,
        (float*)d_out);
}